// round 2
// baseline (speedup 1.0000x reference)
#include <cuda_runtime.h>
#include <cstdint>

// Problem constants
#define NB 64
#define C  128
#define H  56
#define W  56
#define HW (H*W)

// Scratch (static __device__ -> no allocation, graph-capturable)
__device__ uint4  g_xbits[NB * HW];      // [n][h][w] -> 128 sign bits (4 words), bit=1 iff x<0
__device__ __align__(16) uint32_t g_wbits[C * 9 * 4]; // [co][tap][word], bit=1 iff w<0
__device__ float  g_A[C];                // scale_o * gamma * rsqrt(var+eps)
__device__ float  g_B[C];                // beta - mean * gamma * rsqrt(var+eps)

// ---------------------------------------------------------------------------
// Kernel 1: pack sign(x) bits. One thread per pixel, loops 128 channels
// (coalesced across threads for each channel iteration).
// ---------------------------------------------------------------------------
__global__ void pack_kernel(const float* __restrict__ x) {
    int p = blockIdx.x * blockDim.x + threadIdx.x;
    if (p >= NB * HW) return;
    int n  = p / HW;
    int hw = p - n * HW;
    const float* xp = x + (size_t)n * C * HW + hw;
    uint32_t b0 = 0, b1 = 0, b2 = 0, b3 = 0;
#pragma unroll 8
    for (int c = 0; c < 32; c++) {
        b0 |= (__float_as_uint(__ldg(xp + (size_t)(c      ) * HW)) >> 31) << c;
        b1 |= (__float_as_uint(__ldg(xp + (size_t)(c + 32 ) * HW)) >> 31) << c;
        b2 |= (__float_as_uint(__ldg(xp + (size_t)(c + 64 ) * HW)) >> 31) << c;
        b3 |= (__float_as_uint(__ldg(xp + (size_t)(c + 96 ) * HW)) >> 31) << c;
    }
    g_xbits[p] = make_uint4(b0, b1, b2, b3);
}

// ---------------------------------------------------------------------------
// Kernel 2: weight prep. 512 threads: thread = (co, word j). Each thread
// handles 32 input channels x 9 taps; sabs reduced across the 4 j-lanes.
// ---------------------------------------------------------------------------
__global__ void wprep_kernel(const float* __restrict__ wgt,
                             const float* __restrict__ gamma,
                             const float* __restrict__ beta,
                             const float* __restrict__ mean,
                             const float* __restrict__ var) {
    int tid = threadIdx.x;            // 0..511
    int co  = tid >> 2;
    int j   = tid & 3;
    const float* wp = wgt + (size_t)co * (C * 9) + (size_t)(j * 32) * 9;

    uint32_t wb[9];
#pragma unroll
    for (int t = 0; t < 9; t++) wb[t] = 0;
    float sabs = 0.0f;

    for (int c = 0; c < 32; c++) {
#pragma unroll
        for (int t = 0; t < 9; t++) {
            uint32_t u = __float_as_uint(wp[c * 9 + t]);
            sabs += fabsf(__uint_as_float(u));
            wb[t] |= (u >> 31) << c;
        }
    }
    // reduce sabs across the 4 lanes of this co (lanes co*4 .. co*4+3 are
    // contiguous within a warp)
    sabs += __shfl_xor_sync(0xffffffffu, sabs, 1);
    sabs += __shfl_xor_sync(0xffffffffu, sabs, 2);

#pragma unroll
    for (int t = 0; t < 9; t++)
        g_wbits[(co * 9 + t) * 4 + j] = wb[t];

    if (j == 0) {
        float scale = sabs * (1.0f / 1152.0f);
        float inv   = gamma[co] * rsqrtf(var[co] + 1e-5f);
        g_A[co] = scale * inv;
        g_B[co] = beta[co] - mean[co] * inv;
    }
}

// ---------------------------------------------------------------------------
// Kernel 3: binary conv + BN + residual.
// CTA = (n, h): one output row, all 128 output channels. 256 threads:
//   warp&1 selects w-half (w = half*32 + lane), warp>>2.. -> chunk of 32 co.
// xbits rows (h-1,h,h+1) and all weight bits live in smem.
// ---------------------------------------------------------------------------
__global__ __launch_bounds__(256, 4)
void conv_kernel(const float* __restrict__ x, float* __restrict__ out) {
    int nb = blockIdx.x;
    int n  = nb / H;
    int h  = nb - n * H;

    __shared__ uint4 s_x[3 * W];
    __shared__ uint4 s_w[C * 9];
    __shared__ float s_A[C];
    __shared__ float s_B[C];

    int tid = threadIdx.x;

    // stage weights (L2-resident, tiny)
    const uint4* gw = (const uint4*)g_wbits;
    for (int i = tid; i < C * 9; i += 256) s_w[i] = gw[i];
    if (tid < C) { s_A[tid] = g_A[tid]; s_B[tid] = g_B[tid]; }

    bool rv0 = (h > 0), rv2 = (h < H - 1);
    // stage 3 xbit rows
    for (int i = tid; i < 3 * W; i += 256) {
        int r  = i / W;
        int ww = i - r * W;
        bool v = (r == 1) || (r == 0 ? rv0 : rv2);
        if (v) s_x[i] = g_xbits[(size_t)(n * H + (h - 1 + r)) * W + ww];
    }
    __syncthreads();

    int warp  = tid >> 5;
    int lane  = tid & 31;
    int half  = warp & 1;
    int chunk = warp >> 1;           // 0..3 -> 32 output channels each
    int w     = half * 32 + lane;
    if (w >= W) return;              // no syncs after this point

    // gather the 9 tap words for this pixel into registers
    uint4 xv[9];
    unsigned vmask = 0;
    int nvalid = 0;
#pragma unroll
    for (int t = 0; t < 9; t++) {
        const int dh = t / 3;        // 0..2
        const int dw = t % 3;        // 0..2
        int cw = w + dw - 1;
        bool rowok = (dh == 1) || (dh == 0 ? rv0 : rv2);
        bool v = rowok && (cw >= 0) && (cw < W);
        if (v) { xv[t] = s_x[dh * W + cw]; nvalid++; vmask |= (1u << t); }
        else   { xv[t] = make_uint4(0u, 0u, 0u, 0u); }
    }
    const int base = nvalid * 128;

    const float* resid = x   + ((size_t)n * C) * HW + (size_t)h * W + w;
    float*       outp  = out + ((size_t)n * C) * HW + (size_t)h * W + w;

    const int co0 = chunk * 32;
#pragma unroll 4
    for (int k = 0; k < 32; k++) {
        int co = co0 + k;
        // prefetch residual early to hide LDG latency under the popc chain
        float r = resid[(size_t)co * HW];
        int acc = 0;
#pragma unroll
        for (int t = 0; t < 9; t++) {
            if (vmask & (1u << t)) {
                uint4 wv = s_w[co * 9 + t];
                acc += __popc(xv[t].x ^ wv.x) + __popc(xv[t].y ^ wv.y)
                     + __popc(xv[t].z ^ wv.z) + __popc(xv[t].w ^ wv.w);
            }
        }
        float dot = (float)(base - 2 * acc);
        outp[(size_t)co * HW] = fmaf(dot, s_A[co], s_B[co]) + r;
    }
}

// ---------------------------------------------------------------------------
extern "C" void kernel_launch(void* const* d_in, const int* in_sizes, int n_in,
                              void* d_out, int out_size) {
    const float* x     = (const float*)d_in[0];
    const float* wgt   = (const float*)d_in[1];
    const float* gamma = (const float*)d_in[2];
    const float* beta  = (const float*)d_in[3];
    const float* mean  = (const float*)d_in[4];
    const float* var   = (const float*)d_in[5];
    float* out = (float*)d_out;

    (void)in_sizes; (void)n_in; (void)out_size;

    int npix = NB * HW;
    pack_kernel<<<(npix + 255) / 256, 256>>>(x);
    wprep_kernel<<<1, 512>>>(wgt, gamma, beta, mean, var);
    conv_kernel<<<NB * H, 256>>>(x, out);
}

// round 3
// speedup vs baseline: 1.2398x; 1.2398x over previous
#include <cuda_runtime.h>
#include <cstdint>

// Problem constants
#define NB 64
#define C  128
#define H  56
#define W  56
#define HW (H*W)

// Scratch (static __device__ -> no allocation, graph-capturable)
__device__ uint4  g_xbits[NB * HW];      // [n][hw] -> 128 sign bits (4 words), bit=1 iff x<0
__device__ __align__(16) uint32_t g_wbits[C * 9 * 4]; // [co][tap][word], bit=1 iff w<0
__device__ float  g_A[C];                // scale_o * gamma * rsqrt(var+eps)
__device__ float  g_B[C];                // beta - mean * gamma * rsqrt(var+eps)
__device__ float  g_wcnt[C * 9];         // popc(128 sign bits) per (co, tap), as float

// ---------------------------------------------------------------------------
// Kernel 1: pack sign(x) bits. One thread per 4 consecutive pixels (float4
// loads, perfectly coalesced, high MLP).
// ---------------------------------------------------------------------------
__global__ void pack_kernel(const float4* __restrict__ x4) {
    int p4 = blockIdx.x * blockDim.x + threadIdx.x;   // 0 .. NB*HW/4-1
    if (p4 >= NB * (HW / 4)) return;
    int n = p4 / (HW / 4);
    int q = p4 - n * (HW / 4);
    const float4* xp = x4 + (size_t)n * C * (HW / 4) + q;

    uint32_t b0[4] = {0,0,0,0}, b1[4] = {0,0,0,0}, b2[4] = {0,0,0,0}, b3[4] = {0,0,0,0};
#pragma unroll
    for (int word = 0; word < 4; ++word) {
#pragma unroll
        for (int bit = 0; bit < 32; ++bit) {
            float4 v = __ldg(xp + (size_t)(word * 32 + bit) * (HW / 4));
            b0[word] |= (__float_as_uint(v.x) >> 31) << bit;
            b1[word] |= (__float_as_uint(v.y) >> 31) << bit;
            b2[word] |= (__float_as_uint(v.z) >> 31) << bit;
            b3[word] |= (__float_as_uint(v.w) >> 31) << bit;
        }
    }
    uint4* dst = &g_xbits[p4 * 4];
    dst[0] = make_uint4(b0[0], b0[1], b0[2], b0[3]);
    dst[1] = make_uint4(b1[0], b1[1], b1[2], b1[3]);
    dst[2] = make_uint4(b2[0], b2[1], b2[2], b2[3]);
    dst[3] = make_uint4(b3[0], b3[1], b3[2], b3[3]);
}

// ---------------------------------------------------------------------------
// Kernel 2: weight prep. 512 threads: thread = (co, word j). Each thread
// handles 32 input channels x 9 taps; sabs + per-tap popcounts reduced across
// the 4 j-lanes via shuffles.
// ---------------------------------------------------------------------------
__global__ void wprep_kernel(const float* __restrict__ wgt,
                             const float* __restrict__ gamma,
                             const float* __restrict__ beta,
                             const float* __restrict__ mean,
                             const float* __restrict__ var) {
    int tid = threadIdx.x;            // 0..511
    int co  = tid >> 2;
    int j   = tid & 3;
    const float* wp = wgt + (size_t)co * (C * 9) + (size_t)(j * 32) * 9;

    uint32_t wb[9];
#pragma unroll
    for (int t = 0; t < 9; t++) wb[t] = 0;
    float sabs = 0.0f;

    for (int c = 0; c < 32; c++) {
#pragma unroll
        for (int t = 0; t < 9; t++) {
            uint32_t u = __float_as_uint(wp[c * 9 + t]);
            sabs += fabsf(__uint_as_float(u));
            wb[t] |= (u >> 31) << c;
        }
    }
    // reduce sabs across the 4 lanes of this co
    sabs += __shfl_xor_sync(0xffffffffu, sabs, 1);
    sabs += __shfl_xor_sync(0xffffffffu, sabs, 2);

#pragma unroll
    for (int t = 0; t < 9; t++) {
        g_wbits[(co * 9 + t) * 4 + j] = wb[t];
        int pc = __popc(wb[t]);
        pc += __shfl_xor_sync(0xffffffffu, pc, 1);
        pc += __shfl_xor_sync(0xffffffffu, pc, 2);
        if (j == 0) g_wcnt[co * 9 + t] = (float)pc;
    }

    if (j == 0) {
        float scale = sabs * (1.0f / 1152.0f);
        float inv   = gamma[co] * rsqrtf(var[co] + 1e-5f);
        g_A[co] = scale * inv;
        g_B[co] = beta[co] - mean[co] * inv;
    }
}

// ---------------------------------------------------------------------------
// Full adder on bit-planes: 2 LOP3s (sum = a^b^c, carry = maj(a,b,c))
// ---------------------------------------------------------------------------
__device__ __forceinline__ void fadd(uint32_t a, uint32_t b, uint32_t c,
                                     uint32_t& s, uint32_t& cy) {
    s  = a ^ b ^ c;
    cy = (a & b) | (c & (a ^ b));
}

// ---------------------------------------------------------------------------
// Kernel 3: binary conv + BN + residual, CSA-compressed popcount.
// CTA = (n, h). 224 threads: w = tid%56, co-chunk = tid/56 (32 co each).
// x rows staged into padded smem (zeros at borders); exact correction for the
// zero-pad contribution (popc(0^w)=popc(w)) folded into per-co constants.
// Per output: 36 XOR + 40 LOP3 (CSA) + 16 POPC instead of 36 XOR + 36 POPC.
// ---------------------------------------------------------------------------
__global__ __launch_bounds__(224, 2)
void conv_kernel(const float* __restrict__ x, float* __restrict__ out) {
    int nb = blockIdx.x;
    int n  = nb / H;
    int h  = nb - n * H;

    __shared__ uint4  s_x[3 * 58];     // padded: col index = w+1, cols 0 and 57 are zero
    __shared__ uint4  s_w[C * 9];
    __shared__ float4 s_c[C];          // {-2A, A, Kbase = B + 2A*cr_row, Q0 = 2A*c0}
    __shared__ float  s_q2[C];         // 2A*c2

    int tid = threadIdx.x;
    bool hi0 = (h == 0), hi2 = (h == H - 1);

    // stage weights (L2-resident, tiny)
    const uint4* gw = (const uint4*)g_wbits;
    for (int i = tid; i < C * 9; i += 224) s_w[i] = gw[i];

    // stage 3 xbit rows with zero padding
    for (int i = tid; i < 3 * 58; i += 224) {
        int r  = i / 58;
        int cw = i - r * 58 - 1;
        bool rowok = (r == 1) || (r == 0 ? !hi0 : !hi2);
        uint4 v = make_uint4(0u, 0u, 0u, 0u);
        if (rowok && cw >= 0 && cw < W)
            v = g_xbits[(size_t)(n * H + (h - 1 + r)) * W + cw];
        s_x[i] = v;
    }

    // per-co epilogue constants (border corrections folded in)
    if (tid < C) {
        int co = tid;
        float A  = g_A[co];
        float Bv = g_B[co];
        float wc[9];
#pragma unroll
        for (int t = 0; t < 9; t++) wc[t] = g_wcnt[co * 9 + t];
        float cr = (hi0 ? wc[0] + wc[1] + wc[2] : 0.0f)
                 + (hi2 ? wc[6] + wc[7] + wc[8] : 0.0f);
        float c0 = (hi0 ? 0.0f : wc[0]) + wc[3] + (hi2 ? 0.0f : wc[6]);
        float c2 = (hi0 ? 0.0f : wc[2]) + wc[5] + (hi2 ? 0.0f : wc[8]);
        s_c[co]  = make_float4(-2.0f * A, A, fmaf(2.0f * A, cr, Bv), 2.0f * A * c0);
        s_q2[co] = 2.0f * A * c2;
    }
    __syncthreads();

    int w     = tid % 56;
    int chunk = tid / 56;              // 0..3 -> 32 output channels each

    float q0f = (w == 0)     ? 1.0f : 0.0f;
    float q2f = (w == W - 1) ? 1.0f : 0.0f;
    float vr  = 3.0f - (hi0 ? 1.0f : 0.0f) - (hi2 ? 1.0f : 0.0f);
    float vc  = 3.0f - q0f - q2f;
    float nv128 = 128.0f * vr * vc;

    // gather the 9 tap words for this pixel into registers (pads are zero)
    uint4 xv[9];
#pragma unroll
    for (int t = 0; t < 9; t++)
        xv[t] = s_x[(t / 3) * 58 + w + (t % 3)];

    const float* resid = x   + ((size_t)n * C) * HW + (size_t)h * W + w;
    float*       outp  = out + ((size_t)n * C) * HW + (size_t)h * W + w;

    const int co0 = chunk * 32;
#pragma unroll 4
    for (int k = 0; k < 32; k++) {
        int co = co0 + k;
        float r    = resid[(size_t)co * HW];   // prefetch early
        float4 cf  = s_c[co];
        float  q2v = s_q2[co];

        // Level 1: per row-group g, per word j: FA over the 3 taps of the row
        uint32_t sg[3][4], cg[3][4];
#pragma unroll
        for (int g = 0; g < 3; g++) {
            uint4 wv0 = s_w[co * 9 + 3 * g + 0];
            uint4 wv1 = s_w[co * 9 + 3 * g + 1];
            uint4 wv2 = s_w[co * 9 + 3 * g + 2];
            fadd(xv[3*g].x ^ wv0.x, xv[3*g+1].x ^ wv1.x, xv[3*g+2].x ^ wv2.x, sg[g][0], cg[g][0]);
            fadd(xv[3*g].y ^ wv0.y, xv[3*g+1].y ^ wv1.y, xv[3*g+2].y ^ wv2.y, sg[g][1], cg[g][1]);
            fadd(xv[3*g].z ^ wv0.z, xv[3*g+1].z ^ wv1.z, xv[3*g+2].z ^ wv2.z, sg[g][2], cg[g][2]);
            fadd(xv[3*g].w ^ wv0.w, xv[3*g+1].w ^ wv1.w, xv[3*g+2].w ^ wv2.w, sg[g][3], cg[g][3]);
        }
        // Level 2: FA across the 3 row-groups (separately for sums and carries)
        uint32_t ss[4], sc[4], cs[4], cc[4];
#pragma unroll
        for (int j = 0; j < 4; j++) {
            fadd(sg[0][j], sg[1][j], sg[2][j], ss[j], sc[j]);   // w1 -> w1 + w2
            fadd(cg[0][j], cg[1][j], cg[2][j], cs[j], cc[j]);   // w2 -> w2 + w4
        }
        int p1 = __popc(ss[0]) + __popc(ss[1]) + __popc(ss[2]) + __popc(ss[3]);
        int p2 = __popc(sc[0]) + __popc(sc[1]) + __popc(sc[2]) + __popc(sc[3])
               + __popc(cs[0]) + __popc(cs[1]) + __popc(cs[2]) + __popc(cs[3]);
        int p4 = __popc(cc[0]) + __popc(cc[1]) + __popc(cc[2]) + __popc(cc[3]);
        int acc = p1 + 2 * p2 + 4 * p4;    // = sum popc(x^w) over all 9 taps (pads included)

        // out = A*(128*nvalid - 2*(acc - corr)) + B + r, corr folded into constants
        float K = fmaf(cf.y, nv128, cf.z);
        K = fmaf(q0f, cf.w, K);
        K = fmaf(q2f, q2v, K);
        outp[(size_t)co * HW] = fmaf(cf.x, (float)acc, K) + r;
    }
}

// ---------------------------------------------------------------------------
extern "C" void kernel_launch(void* const* d_in, const int* in_sizes, int n_in,
                              void* d_out, int out_size) {
    const float* x     = (const float*)d_in[0];
    const float* wgt   = (const float*)d_in[1];
    const float* gamma = (const float*)d_in[2];
    const float* beta  = (const float*)d_in[3];
    const float* mean  = (const float*)d_in[4];
    const float* var   = (const float*)d_in[5];
    float* out = (float*)d_out;

    (void)in_sizes; (void)n_in; (void)out_size;

    int npix4 = NB * (HW / 4);
    pack_kernel<<<(npix4 + 255) / 256, 256>>>((const float4*)x);
    wprep_kernel<<<1, 512>>>(wgt, gamma, beta, mean, var);
    conv_kernel<<<NB * H, 224>>>(x, out);
}

// round 5
// speedup vs baseline: 1.2918x; 1.0419x over previous
#include <cuda_runtime.h>
#include <cstdint>

// Problem constants
#define NB 64
#define C  128
#define H  56
#define W  56
#define HW (H*W)

// Scratch (static __device__ -> no allocation, graph-capturable)
__device__ uint4  g_xbits[NB * HW];      // [n][hw] -> 128 sign bits (4 words), bit=1 iff x<0
__device__ __align__(16) uint32_t g_wbits[C * 9 * 4]; // [co][tap][word], bit=1 iff w<0
__device__ float  g_A[C];                // scale_o * gamma * rsqrt(var+eps)
__device__ float  g_B[C];                // beta - mean * gamma * rsqrt(var+eps)
__device__ float  g_wcnt[C * 9];         // popc(128 sign bits) per (co, tap), as float

// ---------------------------------------------------------------------------
// Kernel 1: pack sign(x) bits. Thread = (pixel-group q of 4 pixels, word j).
// Each thread: 32 float4 loads (channels j*32..j*32+31), q contiguous within
// a warp -> fully coalesced 512B per load instruction, 32-deep MLP.
// ---------------------------------------------------------------------------
__global__ void pack_kernel(const float4* __restrict__ x4) {
    int t = blockIdx.x * blockDim.x + threadIdx.x;    // 0 .. NB*HW-1  (HW/4 groups * 4 words)
    const int QTOT = NB * (HW / 4);
    int j = t / QTOT;                                  // word 0..3 (blocks of QTOT)
    int q = t - j * QTOT;                              // global 4-pixel group
    if (j >= 4) return;
    int n  = q / (HW / 4);
    int qq = q - n * (HW / 4);
    const float4* xp = x4 + (size_t)n * C * (HW / 4) + (size_t)j * 32 * (HW / 4) + qq;

    uint32_t b[4] = {0, 0, 0, 0};
#pragma unroll
    for (int bit = 0; bit < 32; ++bit) {
        float4 v = __ldg(xp + (size_t)bit * (HW / 4));
        b[0] |= (__float_as_uint(v.x) >> 31) << bit;
        b[1] |= (__float_as_uint(v.y) >> 31) << bit;
        b[2] |= (__float_as_uint(v.z) >> 31) << bit;
        b[3] |= (__float_as_uint(v.w) >> 31) << bit;
    }
    uint32_t* dst = (uint32_t*)g_xbits;
#pragma unroll
    for (int i = 0; i < 4; ++i)
        dst[(size_t)(q * 4 + i) * 4 + j] = b[i];
}

// ---------------------------------------------------------------------------
// Kernel 2: weight prep. 512 threads: thread = (co, word j).
// ---------------------------------------------------------------------------
__global__ void wprep_kernel(const float* __restrict__ wgt,
                             const float* __restrict__ gamma,
                             const float* __restrict__ beta,
                             const float* __restrict__ mean,
                             const float* __restrict__ var) {
    int tid = threadIdx.x;            // 0..511
    int co  = tid >> 2;
    int j   = tid & 3;
    const float* wp = wgt + (size_t)co * (C * 9) + (size_t)(j * 32) * 9;

    uint32_t wb[9];
#pragma unroll
    for (int t = 0; t < 9; t++) wb[t] = 0;
    float sabs = 0.0f;

    for (int c = 0; c < 32; c++) {
#pragma unroll
        for (int t = 0; t < 9; t++) {
            uint32_t u = __float_as_uint(wp[c * 9 + t]);
            sabs += fabsf(__uint_as_float(u));
            wb[t] |= (u >> 31) << c;
        }
    }
    sabs += __shfl_xor_sync(0xffffffffu, sabs, 1);
    sabs += __shfl_xor_sync(0xffffffffu, sabs, 2);

#pragma unroll
    for (int t = 0; t < 9; t++) {
        g_wbits[(co * 9 + t) * 4 + j] = wb[t];
        int pc = __popc(wb[t]);
        pc += __shfl_xor_sync(0xffffffffu, pc, 1);
        pc += __shfl_xor_sync(0xffffffffu, pc, 2);
        if (j == 0) g_wcnt[co * 9 + t] = (float)pc;
    }

    if (j == 0) {
        float scale = sabs * (1.0f / 1152.0f);
        float inv   = gamma[co] * rsqrtf(var[co] + 1e-5f);
        g_A[co] = scale * inv;
        g_B[co] = beta[co] - mean[co] * inv;
    }
}

// ---------------------------------------------------------------------------
// Full adder on bit-planes: sum = a^b^c, carry = maj(a,b,c)  (2 LOP3)
// ---------------------------------------------------------------------------
__device__ __forceinline__ void fadd(uint32_t a, uint32_t b, uint32_t c,
                                     uint32_t& s, uint32_t& cy) {
    s  = a ^ b ^ c;
    cy = (a & b) | (c & (a ^ b));
}

// ---------------------------------------------------------------------------
// Kernel 3: binary conv + BN + residual, single-level CSA popcount.
// CTA = (n, h). 224 threads: w = tid%56, co-chunk = tid/56 (32 co each).
// Per row-group: FA over 3 taps -> popc(sum) + 2*popc(carry).
// Per output: 36 XOR + 24 LOP3 + 24 POPC. Two independent accumulators.
// occ 3 target (21 warps/SM) for latency hiding.
// ---------------------------------------------------------------------------
__global__ __launch_bounds__(224, 3)
void conv_kernel(const float* __restrict__ x, float* __restrict__ out) {
    int nb = blockIdx.x;
    int n  = nb / H;
    int h  = nb - n * H;

    __shared__ uint4  s_x[3 * 58];     // padded: col = w+1, cols 0/57 zero
    __shared__ uint4  s_w[C * 9];
    __shared__ float4 s_c[C];          // {-2A, A, Kbase, Q0}
    __shared__ float  s_q2[C];         // 2A*c2

    int tid = threadIdx.x;
    bool hi0 = (h == 0), hi2 = (h == H - 1);

    const uint4* gw = (const uint4*)g_wbits;
    for (int i = tid; i < C * 9; i += 224) s_w[i] = gw[i];

    for (int i = tid; i < 3 * 58; i += 224) {
        int r  = i / 58;
        int cw = i - r * 58 - 1;
        bool rowok = (r == 1) || (r == 0 ? !hi0 : !hi2);
        uint4 v = make_uint4(0u, 0u, 0u, 0u);
        if (rowok && cw >= 0 && cw < W)
            v = g_xbits[(size_t)(n * H + (h - 1 + r)) * W + cw];
        s_x[i] = v;
    }

    if (tid < C) {
        int co = tid;
        float A  = g_A[co];
        float Bv = g_B[co];
        float wc[9];
#pragma unroll
        for (int t = 0; t < 9; t++) wc[t] = g_wcnt[co * 9 + t];
        float cr = (hi0 ? wc[0] + wc[1] + wc[2] : 0.0f)
                 + (hi2 ? wc[6] + wc[7] + wc[8] : 0.0f);
        float c0 = (hi0 ? 0.0f : wc[0]) + wc[3] + (hi2 ? 0.0f : wc[6]);
        float c2 = (hi0 ? 0.0f : wc[2]) + wc[5] + (hi2 ? 0.0f : wc[8]);
        s_c[co]  = make_float4(-2.0f * A, A, fmaf(2.0f * A, cr, Bv), 2.0f * A * c0);
        s_q2[co] = 2.0f * A * c2;
    }
    __syncthreads();

    int w     = tid % 56;
    int chunk = tid / 56;              // 0..3 -> 32 output channels each

    float q0f = (w == 0)     ? 1.0f : 0.0f;
    float q2f = (w == W - 1) ? 1.0f : 0.0f;
    float vr  = 3.0f - (hi0 ? 1.0f : 0.0f) - (hi2 ? 1.0f : 0.0f);
    float vc  = 3.0f - q0f - q2f;
    float nv128 = 128.0f * vr * vc;

    // 9 tap words for this pixel (pads are zero)
    uint4 xv[9];
#pragma unroll
    for (int t = 0; t < 9; t++)
        xv[t] = s_x[(t / 3) * 58 + w + (t % 3)];

    const float* resid = x   + ((size_t)n * C) * HW + (size_t)h * W + w;
    float*       outp  = out + ((size_t)n * C) * HW + (size_t)h * W + w;

    const int co0 = chunk * 32;
#pragma unroll 4
    for (int k = 0; k < 32; k++) {
        int co = co0 + k;
        float r    = resid[(size_t)co * HW];   // prefetch early
        float4 cf  = s_c[co];
        float  q2v = s_q2[co];

        int acc1 = 0, acc2 = 0;                // weight-1 and weight-2 popc sums
#pragma unroll
        for (int g = 0; g < 3; g++) {
            uint4 wv0 = s_w[co * 9 + 3 * g + 0];
            uint4 wv1 = s_w[co * 9 + 3 * g + 1];
            uint4 wv2 = s_w[co * 9 + 3 * g + 2];
            uint32_t s0, c0, s1, c1, s2, c2, s3, c3;
            fadd(xv[3*g].x ^ wv0.x, xv[3*g+1].x ^ wv1.x, xv[3*g+2].x ^ wv2.x, s0, c0);
            fadd(xv[3*g].y ^ wv0.y, xv[3*g+1].y ^ wv1.y, xv[3*g+2].y ^ wv2.y, s1, c1);
            fadd(xv[3*g].z ^ wv0.z, xv[3*g+1].z ^ wv1.z, xv[3*g+2].z ^ wv2.z, s2, c2);
            fadd(xv[3*g].w ^ wv0.w, xv[3*g+1].w ^ wv1.w, xv[3*g+2].w ^ wv2.w, s3, c3);
            acc1 += __popc(s0) + __popc(s1) + __popc(s2) + __popc(s3);
            acc2 += __popc(c0) + __popc(c1) + __popc(c2) + __popc(c3);
        }
        int acc = acc1 + 2 * acc2;             // = sum popc(x^w) over all 9 taps

        float K = fmaf(cf.y, nv128, cf.z);
        K = fmaf(q0f, cf.w, K);
        K = fmaf(q2f, q2v, K);
        outp[(size_t)co * HW] = fmaf(cf.x, (float)acc, K) + r;
    }
}

// ---------------------------------------------------------------------------
extern "C" void kernel_launch(void* const* d_in, const int* in_sizes, int n_in,
                              void* d_out, int out_size) {
    const float* x     = (const float*)d_in[0];
    const float* wgt   = (const float*)d_in[1];
    const float* gamma = (const float*)d_in[2];
    const float* beta  = (const float*)d_in[3];
    const float* mean  = (const float*)d_in[4];
    const float* var   = (const float*)d_in[5];
    float* out = (float*)d_out;

    (void)in_sizes; (void)n_in; (void)out_size;

    int nthreads = NB * HW;               // (HW/4 groups) * 4 words per batch
    pack_kernel<<<(nthreads + 255) / 256, 256>>>((const float4*)x);
    wprep_kernel<<<1, 512>>>(wgt, gamma, beta, mean, var);
    conv_kernel<<<NB * H, 224>>>(x, out);
}